// round 15
// baseline (speedup 1.0000x reference)
#include <cuda_runtime.h>
#include <cuda_bf16.h>
#include <stdint.h>
#include <math.h>

#define S_LEN 2048
#define HID   2048
#define NH    16
#define HD    128
#define BATCH 2
#define MROWS 4096
#define NBH   32
#define G_STAGE   32768
#define G_NST     3
#define SMEM_GEMM (G_NST * G_STAGE)
#define SMEM_FLASH 98304

// ---------------- scratch globals ------------------------------------------
__device__ __align__(16) __nv_bfloat16 g_Xhi[MROWS * HID];
__device__ __align__(16) __nv_bfloat16 g_Xlo[MROWS * HID];
__device__ __align__(16) __nv_bfloat16 g_Whi[4][HID * HID];
__device__ __align__(16) __nv_bfloat16 g_Wlo[4][HID * HID];
__device__ __align__(16) __nv_bfloat16 g_Qhi[NBH * S_LEN * HD];
__device__ __align__(16) __nv_bfloat16 g_Qlo[NBH * S_LEN * HD];
__device__ __align__(16) __nv_bfloat16 g_Khi[NBH * S_LEN * HD];
__device__ __align__(16) __nv_bfloat16 g_Klo[NBH * S_LEN * HD];
__device__ __align__(16) __nv_bfloat16 g_Vhi[NBH * S_LEN * HD];
__device__ __align__(16) __nv_bfloat16 g_Vlo[NBH * S_LEN * HD];
__device__ __align__(16) __nv_bfloat16 g_Chi[MROWS * HID];
__device__ __align__(16) __nv_bfloat16 g_Clo[MROWS * HID];

// ---------------- helpers ---------------------------------------------------
__device__ __forceinline__ uint32_t smem_u32(const void* p) {
    uint32_t a;
    asm("{ .reg .u64 t; cvta.to.shared.u64 t, %1; cvt.u32.u64 %0, t; }"
        : "=r"(a) : "l"(p));
    return a;
}
#define SWZ(o) ((o) ^ (((o) >> 3) & 0x70))
#define CP16(dst, src) \
    asm volatile("cp.async.cg.shared.global [%0], [%1], 16;" \
                 :: "r"((uint32_t)(dst)), "l"(src) : "memory")

__device__ __forceinline__ void ldsm_x4(uint32_t r[4], uint32_t addr) {
    asm volatile("ldmatrix.sync.aligned.m8n8.x4.shared.b16 {%0,%1,%2,%3}, [%4];"
        : "=r"(r[0]), "=r"(r[1]), "=r"(r[2]), "=r"(r[3]) : "r"(addr));
}
__device__ __forceinline__ void ldsm_x4t(uint32_t r[4], uint32_t addr) {
    asm volatile("ldmatrix.sync.aligned.m8n8.x4.trans.shared.b16 {%0,%1,%2,%3}, [%4];"
        : "=r"(r[0]), "=r"(r[1]), "=r"(r[2]), "=r"(r[3]) : "r"(addr));
}
__device__ __forceinline__ void mma16816(float d[4], const uint32_t a[4],
                                         const uint32_t b0, const uint32_t b1) {
    asm volatile("mma.sync.aligned.m16n8k16.row.col.f32.bf16.bf16.f32 "
        "{%0,%1,%2,%3}, {%4,%5,%6,%7}, {%8,%9}, {%0,%1,%2,%3};"
        : "+f"(d[0]), "+f"(d[1]), "+f"(d[2]), "+f"(d[3])
        : "r"(a[0]), "r"(a[1]), "r"(a[2]), "r"(a[3]), "r"(b0), "r"(b1));
}
__device__ __forceinline__ uint32_t packbf(float a, float b) {
    __nv_bfloat162 t = __floats2bfloat162_rn(a, b);
    return *(uint32_t*)&t;
}
__device__ __forceinline__ void split2pack(float a, float b, uint32_t& hi, uint32_t& lo) {
    __nv_bfloat16 ha = __float2bfloat16_rn(a);
    __nv_bfloat16 hb = __float2bfloat16_rn(b);
    hi = ((uint32_t)*(unsigned short*)&hb << 16) | *(unsigned short*)&ha;
    lo = packbf(a - __bfloat162float(ha), b - __bfloat162float(hb));
}

// ---------------- fused fp32 -> bf16 hi/lo conversion (8 elems/thread) -------
__global__ void conv_kernel(const float* __restrict__ X,
                            const float* __restrict__ Wq, const float* __restrict__ Wk,
                            const float* __restrict__ Wv, const float* __restrict__ Wo)
{
    const int XN = MROWS * HID;
    const int WN = HID * HID;
    int i8 = (blockIdx.x * 256 + threadIdx.x) * 8;
    const float* src;
    __nv_bfloat16 *dh, *dl;
    int off;
    if (i8 < XN) { src = X; dh = g_Xhi; dl = g_Xlo; off = i8; }
    else {
        int j = i8 - XN;
        int w = j / WN; off = j - w * WN;
        src = (w == 0) ? Wq : (w == 1) ? Wk : (w == 2) ? Wv : Wo;
        dh = g_Whi[w]; dl = g_Wlo[w];
    }
    float4 v0 = *(const float4*)(src + off);
    float4 v1 = *(const float4*)(src + off + 4);
    uint32_t h01, l01, h23, l23, h45, l45, h67, l67;
    split2pack(v0.x, v0.y, h01, l01);
    split2pack(v0.z, v0.w, h23, l23);
    split2pack(v1.x, v1.y, h45, l45);
    split2pack(v1.z, v1.w, h67, l67);
    *(uint4*)(dh + off) = make_uint4(h01, h23, h45, h67);
    *(uint4*)(dl + off) = make_uint4(l01, l23, l45, l67);
}

// ---------------- projection / out-proj GEMM ---------------------------------
// 128x128 tile, K-chunk 32, hi|lo packed rows, 3-stage ring, 1 barrier/chunk,
// lookahead-2, 2 CTAs/SM. RoPE fused into the Q/K epilogue.
__global__ __launch_bounds__(256, 2) void gemm_kernel(int mode, float* __restrict__ out)
{
    extern __shared__ char smem[];
    uint32_t sb = smem_u32(smem);

    int tid = threadIdx.x;
    int wid = tid >> 5, lane = tid & 31;
    int wm = wid & 3, wn = wid >> 2;
    int t = blockIdx.x;

    const __nv_bfloat16 *Ahi, *Alo, *Bhi, *Blo;
    int mtile, ntile, w = 0;
    const int nChunks = 64;

    if (mode == 0) {
        w = t >> 9; int r = t & 511; mtile = r >> 4; ntile = r & 15;
        Ahi = g_Xhi + (size_t)mtile * 128 * HID;
        Alo = g_Xlo + (size_t)mtile * 128 * HID;
        Bhi = g_Whi[w] + (size_t)ntile * 128 * HID;
        Blo = g_Wlo[w] + (size_t)ntile * 128 * HID;
    } else {
        mtile = t >> 4; ntile = t & 15;
        Ahi = g_Chi + (size_t)mtile * 128 * HID;
        Alo = g_Clo + (size_t)mtile * 128 * HID;
        Bhi = g_Whi[3] + (size_t)ntile * 128 * HID;
        Blo = g_Wlo[3] + (size_t)ntile * 128 * HID;
    }

    int lrow[8], lseg[8], lmat[8], lhl[8];
    uint32_t ldst[8];
#pragma unroll
    for (int it = 0; it < 8; it++) {
        int u = tid + it * 256;
        int mat = u >> 10, hl = (u >> 9) & 1, row = (u >> 2) & 127, seg = u & 3;
        lmat[it] = mat; lhl[it] = hl; lrow[it] = row; lseg[it] = seg;
        ldst[it] = mat * 16384 + SWZ(row * 128 + hl * 64 + seg * 16);
    }

    float acc[2][8][4];
#pragma unroll
    for (int mi = 0; mi < 2; mi++)
#pragma unroll
        for (int ni = 0; ni < 8; ni++)
#pragma unroll
            for (int e = 0; e < 4; e++) acc[mi][ni][e] = 0.0f;

    auto issue_load = [&](int c) {
        int koff = c * 32;
        uint32_t base = sb + (c % G_NST) * G_STAGE;
#pragma unroll
        for (int it = 0; it < 8; it++) {
            const __nv_bfloat16* src0 =
                (lmat[it] == 0) ? (lhl[it] ? Alo : Ahi)
                                : (lhl[it] ? Blo : Bhi);
            const __nv_bfloat16* src = src0 + (size_t)lrow[it] * HID + koff + lseg[it] * 8;
            CP16(base + ldst[it], src);
        }
        asm volatile("cp.async.commit_group;" ::: "memory");
    };

    issue_load(0); issue_load(1);

    int a_r = lane & 15, a_h = (lane >> 4) << 4;
    int b_r = lane & 7;
    int b_row = ((lane >> 4) << 3) + b_r;
    int b_h = ((lane >> 3) & 1) << 4;

    for (int c = 0; c < nChunks; c++) {
        if (c + 1 < nChunks) {
            asm volatile("cp.async.wait_group 1;" ::: "memory");
        } else {
            asm volatile("cp.async.wait_group 0;" ::: "memory");
        }
        __syncthreads();

        if (c + 2 < nChunks) issue_load(c + 2);

        uint32_t st = sb + (c % G_NST) * G_STAGE;
        uint32_t aB = st, bB = st + 16384;

#pragma unroll
        for (int kk = 0; kk < 2; kk++) {
            uint32_t ahi[2][4], alo[2][4];
#pragma unroll
            for (int mi = 0; mi < 2; mi++) {
                int row = wm * 32 + mi * 16 + a_r;
                ldsm_x4(ahi[mi], aB + SWZ(row * 128 + kk * 32 + a_h));
                ldsm_x4(alo[mi], aB + SWZ(row * 128 + 64 + kk * 32 + a_h));
            }
#pragma unroll
            for (int np = 0; np < 4; np++) {
                int row = wn * 64 + np * 16 + b_row;
                uint32_t bh[4], bl[4];
                ldsm_x4(bh, bB + SWZ(row * 128 + kk * 32 + b_h));
                ldsm_x4(bl, bB + SWZ(row * 128 + 64 + kk * 32 + b_h));
#pragma unroll
                for (int mi = 0; mi < 2; mi++) {
                    mma16816(acc[mi][2 * np],     ahi[mi], bh[0], bh[1]);
                    mma16816(acc[mi][2 * np + 1], ahi[mi], bh[2], bh[3]);
                    mma16816(acc[mi][2 * np],     ahi[mi], bl[0], bl[1]);
                    mma16816(acc[mi][2 * np + 1], ahi[mi], bl[2], bl[3]);
                    mma16816(acc[mi][2 * np],     alo[mi], bh[0], bh[1]);
                    mma16816(acc[mi][2 * np + 1], alo[mi], bh[2], bh[3]);
                }
            }
        }
    }

    int g = lane >> 2, tq = lane & 3;

    if (mode == 0 && w < 2) {
        // ---- fused RoPE epilogue: stage fp32 tile in smem, rotate, split ----
        float* sf = (float*)smem;
        __syncthreads();
        if (tid < 64)
            sf[16640 + tid] = (float)(1.0 / pow(10000.0, (double)(2 * tid) / 128.0));
#pragma unroll
        for (int mi = 0; mi < 2; mi++)
#pragma unroll
            for (int ni = 0; ni < 8; ni++) {
                int col0 = wn * 64 + ni * 8 + 2 * tq;
#pragma unroll
                for (int half = 0; half < 2; half++) {
                    int row = wm * 32 + mi * 16 + g + half * 8;
                    *(float2*)&sf[row * 130 + col0] =
                        make_float2(acc[mi][ni][2 * half], acc[mi][ni][2 * half + 1]);
                }
            }
        __syncthreads();

        __nv_bfloat16* dh = (w == 0) ? g_Qhi : g_Khi;
        __nv_bfloat16* dl = (w == 0) ? g_Qlo : g_Klo;
        for (int u = tid; u < 128 * 32; u += 256) {
            int r = u >> 5;
            int ip = (u & 31) * 2;
            float x1a = sf[r * 130 + ip],      x1b = sf[r * 130 + ip + 1];
            float x2a = sf[r * 130 + 64 + ip], x2b = sf[r * 130 + 65 + ip];
            int m = mtile * 128 + r;
            int b = m >> 11, sx = m & 2047;
            float fa = (float)sx;
            float anga = fa * sf[16640 + ip];
            float angb = fa * sf[16640 + ip + 1];
            float ca = cosf(anga), sa_ = sinf(anga);
            float cb = cosf(angb), sb_ = sinf(angb);
            float y1a = x1a * ca - x2a * sa_;
            float y2a = x2a * ca + x1a * sa_;
            float y1b = x1b * cb - x2b * sb_;
            float y2b = x2b * cb + x1b * sb_;
            size_t o = ((size_t)(b * NH + ntile) * S_LEN + sx) * HD;
            uint32_t hi, lo;
            split2pack(y1a, y1b, hi, lo);
            *(uint32_t*)(dh + o + ip) = hi;
            *(uint32_t*)(dl + o + ip) = lo;
            split2pack(y2a, y2b, hi, lo);
            *(uint32_t*)(dh + o + 64 + ip) = hi;
            *(uint32_t*)(dl + o + 64 + ip) = lo;
        }
        return;
    }

    // ---- direct epilogue: V (mode 0, w==2) and out-proj (mode 3) ----
#pragma unroll
    for (int mi = 0; mi < 2; mi++) {
#pragma unroll
        for (int ni = 0; ni < 8; ni++) {
            int col0 = wn * 64 + ni * 8 + 2 * tq;
#pragma unroll
            for (int half = 0; half < 2; half++) {
                int row = wm * 32 + mi * 16 + g + half * 8;
                float v0 = acc[mi][ni][2 * half];
                float v1 = acc[mi][ni][2 * half + 1];
                if (mode == 0) {
                    int m = mtile * 128 + row;
                    int b = m >> 11, sx = m & 2047;
                    size_t o = ((size_t)(b * NH + ntile) * S_LEN + sx) * HD + col0;
                    uint32_t hi, lo;
                    split2pack(v0, v1, hi, lo);
                    *(uint32_t*)(g_Vhi + o) = hi;
                    *(uint32_t*)(g_Vlo + o) = lo;
                } else {
                    int m = mtile * 128 + row;
                    *(float2*)(out + (size_t)m * HID + ntile * 128 + col0)
                        = make_float2(v0, v1);
                }
            }
        }
    }
}

// ---------------- fused flash attention: 64-row tiles, 2 CTAs/SM ------------
// Diagonal tiles skip fully-masked 16-col blocks (exact: mask/exp make them 0).
__global__ __launch_bounds__(128, 2) void flash_kernel()
{
    extern __shared__ char smem[];
    uint32_t sb = smem_u32(smem);
    const uint32_t Qh = sb,          Ql = sb + 16384;
    const uint32_t Kh = sb + 32768,  Kl = sb + 49152;
    const uint32_t Vh = sb + 65536,  Vl = sb + 81920;

    int qt = 31 - blockIdx.x;
    int z = blockIdx.y;
    int tid = threadIdx.x, wid = tid >> 5, lane = tid & 31;
    int g = lane >> 2, tq = lane & 3;

    const __nv_bfloat16* Qhg = g_Qhi + ((size_t)z * S_LEN + qt * 64) * HD;
    const __nv_bfloat16* Qlg = g_Qlo + ((size_t)z * S_LEN + qt * 64) * HD;
    const __nv_bfloat16* Khg = g_Khi + (size_t)z * S_LEN * HD;
    const __nv_bfloat16* Klg = g_Klo + (size_t)z * S_LEN * HD;
    const __nv_bfloat16* Vhg = g_Vhi + (size_t)z * S_LEN * HD;
    const __nv_bfloat16* Vlg = g_Vlo + (size_t)z * S_LEN * HD;

    auto load_mat = [&](uint32_t dstbase, const __nv_bfloat16* src) {
#pragma unroll
        for (int it = 0; it < 8; it++) {
            int u = tid + it * 128;
            int row = u >> 4, c = u & 15;
            uint32_t dst = dstbase + ((c >> 3) << 13) + SWZ(row * 128 + (c & 7) * 16);
            CP16(dst, src + (size_t)row * HD + c * 8);
        }
    };

    load_mat(Qh, Qhg); load_mat(Ql, Qlg);
    asm volatile("cp.async.commit_group;" ::: "memory");
    load_mat(Kh, Khg); load_mat(Kl, Klg);
    asm volatile("cp.async.commit_group;" ::: "memory");
    load_mat(Vh, Vhg); load_mat(Vl, Vlg);
    asm volatile("cp.async.commit_group;" ::: "memory");

    float oc[16][4];
#pragma unroll
    for (int j = 0; j < 16; j++)
#pragma unroll
        for (int e = 0; e < 4; e++) oc[j][e] = 0.0f;
    float m0 = -3.4e38f, m1 = -3.4e38f, l0 = 0.0f, l1 = 0.0f;

    const float scale = 0.08838834764831845f;
    int a_r = lane & 15, a_h = (lane >> 4) << 4;
    int bsel = lane >> 3, br = lane & 7;

    for (int kt = 0; kt <= qt; kt++) {
        bool diag = (kt == qt);
        asm volatile("cp.async.wait_group 1;" ::: "memory");
        __syncthreads();

        float s[8][4];
#pragma unroll
        for (int j = 0; j < 8; j++)
#pragma unroll
            for (int e = 0; e < 4; e++) s[j][e] = 0.0f;

#pragma unroll
        for (int kk = 0; kk < 8; kk++) {
            int arow = wid * 16 + a_r;
            uint32_t aoff = ((kk >> 2) << 13) + SWZ(arow * 128 + (kk & 3) * 32 + a_h);
            uint32_t ah[4], al[4];
            ldsm_x4(ah, Qh + aoff);
            ldsm_x4(al, Ql + aoff);
#pragma unroll
            for (int jp = 0; jp < 4; jp++) {
                if (diag && jp > wid) continue;   // fully masked block: skip
                int srow = jp * 16 + ((bsel >> 1) << 3) + br;
                uint32_t boff = ((kk >> 2) << 13)
                              + SWZ(srow * 128 + (kk & 3) * 32 + ((bsel & 1) << 4));
                uint32_t bh[4], bl[4];
                ldsm_x4(bh, Kh + boff);
                ldsm_x4(bl, Kl + boff);
                mma16816(s[2 * jp],     ah, bh[0], bh[1]);
                mma16816(s[2 * jp + 1], ah, bh[2], bh[3]);
                mma16816(s[2 * jp],     ah, bl[0], bl[1]);
                mma16816(s[2 * jp + 1], ah, bl[2], bl[3]);
                mma16816(s[2 * jp],     al, bh[0], bh[1]);
                mma16816(s[2 * jp + 1], al, bh[2], bh[3]);
            }
        }

        int row0 = qt * 64 + wid * 16 + g;
        float tm0 = -3.4e38f, tm1 = -3.4e38f;
#pragma unroll
        for (int j = 0; j < 8; j++) {
#pragma unroll
            for (int e = 0; e < 4; e++) {
                float v = s[j][e] * scale;
                if (diag) {
                    int col = kt * 64 + j * 8 + 2 * tq + (e & 1);
                    int row = row0 + ((e >> 1) << 3);
                    if (col > row) v = -3.0e38f;
                }
                s[j][e] = v;
                if (e < 2) tm0 = fmaxf(tm0, v); else tm1 = fmaxf(tm1, v);
            }
        }
        tm0 = fmaxf(tm0, __shfl_xor_sync(0xffffffffu, tm0, 1));
        tm0 = fmaxf(tm0, __shfl_xor_sync(0xffffffffu, tm0, 2));
        tm1 = fmaxf(tm1, __shfl_xor_sync(0xffffffffu, tm1, 1));
        tm1 = fmaxf(tm1, __shfl_xor_sync(0xffffffffu, tm1, 2));
        float nm0 = fmaxf(m0, tm0), nm1 = fmaxf(m1, tm1);
        float f0 = __expf(m0 - nm0), f1 = __expf(m1 - nm1);

        float ts0 = 0.0f, ts1 = 0.0f;
        uint32_t phi[4][4], plo[4][4];
#pragma unroll
        for (int i = 0; i < 4; i++) {
            float p[2][4];
#pragma unroll
            for (int h = 0; h < 2; h++) {
                int j = 2 * i + h;
                p[h][0] = __expf(s[j][0] - nm0);
                p[h][1] = __expf(s[j][1] - nm0);
                p[h][2] = __expf(s[j][2] - nm1);
                p[h][3] = __expf(s[j][3] - nm1);
                ts0 += p[h][0] + p[h][1];
                ts1 += p[h][2] + p[h][3];
            }
            phi[i][0] = packbf(p[0][0], p[0][1]);
            phi[i][1] = packbf(p[0][2], p[0][3]);
            phi[i][2] = packbf(p[1][0], p[1][1]);
            phi[i][3] = packbf(p[1][2], p[1][3]);
#pragma unroll
            for (int r = 0; r < 4; r++) {
                __nv_bfloat162 hb = *(__nv_bfloat162*)&phi[i][r];
                float e0 = ((r & 2) ? p[1] : p[0])[(r & 1) ? 2 : 0] - __bfloat162float(hb.x);
                float e1 = ((r & 2) ? p[1] : p[0])[(r & 1) ? 3 : 1] - __bfloat162float(hb.y);
                plo[i][r] = packbf(e0, e1);
            }
        }
        ts0 += __shfl_xor_sync(0xffffffffu, ts0, 1);
        ts0 += __shfl_xor_sync(0xffffffffu, ts0, 2);
        ts1 += __shfl_xor_sync(0xffffffffu, ts1, 1);
        ts1 += __shfl_xor_sync(0xffffffffu, ts1, 2);
        l0 = l0 * f0 + ts0;
        l1 = l1 * f1 + ts1;
        m0 = nm0; m1 = nm1;
#pragma unroll
        for (int j = 0; j < 16; j++) {
            oc[j][0] *= f0; oc[j][1] *= f0; oc[j][2] *= f1; oc[j][3] *= f1;
        }

        asm volatile("cp.async.wait_group 0;" ::: "memory");
        __syncthreads();
        if (kt < qt) {
            load_mat(Kh, Khg + (size_t)(kt + 1) * 64 * HD);
            load_mat(Kl, Klg + (size_t)(kt + 1) * 64 * HD);
            asm volatile("cp.async.commit_group;" ::: "memory");
        }

#pragma unroll
        for (int i = 0; i < 4; i++) {
            if (diag && i > wid) continue;       // P exactly 0 there: skip
            int krow = i * 16 + ((bsel & 1) << 3) + br;
#pragma unroll
            for (int dp = 0; dp < 8; dp++) {
                int dt = 2 * dp + (bsel >> 1);
                uint32_t voff = ((dt >> 3) << 13) + SWZ(krow * 128 + (dt & 7) * 16);
                uint32_t vh[4], vl[4];
                ldsm_x4t(vh, Vh + voff);
                ldsm_x4t(vl, Vl + voff);
                mma16816(oc[2 * dp],     phi[i], vh[0], vh[1]);
                mma16816(oc[2 * dp + 1], phi[i], vh[2], vh[3]);
                mma16816(oc[2 * dp],     phi[i], vl[0], vl[1]);
                mma16816(oc[2 * dp + 1], phi[i], vl[2], vl[3]);
                mma16816(oc[2 * dp],     plo[i], vh[0], vh[1]);
                mma16816(oc[2 * dp + 1], plo[i], vh[2], vh[3]);
            }
        }
        __syncthreads();
        if (kt < qt) {
            load_mat(Vh, Vhg + (size_t)(kt + 1) * 64 * HD);
            load_mat(Vl, Vlg + (size_t)(kt + 1) * 64 * HD);
            asm volatile("cp.async.commit_group;" ::: "memory");
        }
    }

    float inv0 = 1.0f / l0, inv1 = 1.0f / l1;
    int b = z >> 4, hh = z & 15;
    int q0 = qt * 64 + wid * 16 + g;
#pragma unroll
    for (int dt = 0; dt < 16; dt++) {
        int col0 = dt * 8 + 2 * tq;
        size_t o0 = ((size_t)b * S_LEN + q0) * HID + hh * HD + col0;
        size_t o1 = ((size_t)b * S_LEN + q0 + 8) * HID + hh * HD + col0;
        uint32_t hi, lo;
        split2pack(oc[dt][0] * inv0, oc[dt][1] * inv0, hi, lo);
        *(uint32_t*)(g_Chi + o0) = hi;
        *(uint32_t*)(g_Clo + o0) = lo;
        split2pack(oc[dt][2] * inv1, oc[dt][3] * inv1, hi, lo);
        *(uint32_t*)(g_Chi + o1) = hi;
        *(uint32_t*)(g_Clo + o1) = lo;
    }
}

// ---------------------------------------------------------------------------
extern "C" void kernel_launch(void* const* d_in, const int* in_sizes, int n_in,
                              void* d_out, int out_size)
{
    (void)in_sizes; (void)n_in; (void)out_size;
    const float* X  = (const float*)d_in[0];
    const float* Wq = (const float*)d_in[3];
    const float* Wk = (const float*)d_in[4];
    const float* Wv = (const float*)d_in[5];
    const float* Wo = (const float*)d_in[6];
    float* out = (float*)d_out;

    cudaFuncSetAttribute(gemm_kernel,
                         cudaFuncAttributeMaxDynamicSharedMemorySize, SMEM_GEMM);
    cudaFuncSetAttribute(flash_kernel,
                         cudaFuncAttributeMaxDynamicSharedMemorySize, SMEM_FLASH);

    conv_kernel<<<12288, 256>>>(X, Wq, Wk, Wv, Wo);
    gemm_kernel<<<1536, 256, SMEM_GEMM>>>(0, nullptr);     // QKV proj + fused RoPE
    flash_kernel<<<dim3(32, 32), 128, SMEM_FLASH>>>();     // fused attention
    gemm_kernel<<<512, 256, SMEM_GEMM>>>(3, out);          // out proj
}

// round 16
// speedup vs baseline: 1.0257x; 1.0257x over previous
#include <cuda_runtime.h>
#include <cuda_bf16.h>
#include <stdint.h>
#include <math.h>

#define S_LEN 2048
#define HID   2048
#define NH    16
#define HD    128
#define BATCH 2
#define MROWS 4096
#define NBH   32
#define G_STAGE   32768
#define G_NST     3
#define SMEM_GEMM (G_NST * G_STAGE)
#define SMEM_FLASH 98304

// ---------------- scratch globals ------------------------------------------
__device__ __align__(16) __nv_bfloat16 g_Xhi[MROWS * HID];
__device__ __align__(16) __nv_bfloat16 g_Xlo[MROWS * HID];
__device__ __align__(16) __nv_bfloat16 g_Whi[4][HID * HID];
__device__ __align__(16) __nv_bfloat16 g_Wlo[4][HID * HID];
__device__ __align__(16) __nv_bfloat16 g_Qhi[NBH * S_LEN * HD];
__device__ __align__(16) __nv_bfloat16 g_Qlo[NBH * S_LEN * HD];
__device__ __align__(16) __nv_bfloat16 g_Khi[NBH * S_LEN * HD];
__device__ __align__(16) __nv_bfloat16 g_Klo[NBH * S_LEN * HD];
__device__ __align__(16) __nv_bfloat16 g_Vhi[NBH * S_LEN * HD];
__device__ __align__(16) __nv_bfloat16 g_Vlo[NBH * S_LEN * HD];
__device__ __align__(16) __nv_bfloat16 g_Chi[MROWS * HID];
__device__ __align__(16) __nv_bfloat16 g_Clo[MROWS * HID];

// ---------------- helpers ---------------------------------------------------
__device__ __forceinline__ uint32_t smem_u32(const void* p) {
    uint32_t a;
    asm("{ .reg .u64 t; cvta.to.shared.u64 t, %1; cvt.u32.u64 %0, t; }"
        : "=r"(a) : "l"(p));
    return a;
}
#define SWZ(o) ((o) ^ (((o) >> 3) & 0x70))
#define CP16(dst, src) \
    asm volatile("cp.async.cg.shared.global [%0], [%1], 16;" \
                 :: "r"((uint32_t)(dst)), "l"(src) : "memory")

__device__ __forceinline__ void ldsm_x4(uint32_t r[4], uint32_t addr) {
    asm volatile("ldmatrix.sync.aligned.m8n8.x4.shared.b16 {%0,%1,%2,%3}, [%4];"
        : "=r"(r[0]), "=r"(r[1]), "=r"(r[2]), "=r"(r[3]) : "r"(addr));
}
__device__ __forceinline__ void ldsm_x4t(uint32_t r[4], uint32_t addr) {
    asm volatile("ldmatrix.sync.aligned.m8n8.x4.trans.shared.b16 {%0,%1,%2,%3}, [%4];"
        : "=r"(r[0]), "=r"(r[1]), "=r"(r[2]), "=r"(r[3]) : "r"(addr));
}
__device__ __forceinline__ void mma16816(float d[4], const uint32_t a[4],
                                         const uint32_t b0, const uint32_t b1) {
    asm volatile("mma.sync.aligned.m16n8k16.row.col.f32.bf16.bf16.f32 "
        "{%0,%1,%2,%3}, {%4,%5,%6,%7}, {%8,%9}, {%0,%1,%2,%3};"
        : "+f"(d[0]), "+f"(d[1]), "+f"(d[2]), "+f"(d[3])
        : "r"(a[0]), "r"(a[1]), "r"(a[2]), "r"(a[3]), "r"(b0), "r"(b1));
}
__device__ __forceinline__ uint32_t packbf(float a, float b) {
    __nv_bfloat162 t = __floats2bfloat162_rn(a, b);
    return *(uint32_t*)&t;
}
__device__ __forceinline__ void split2pack(float a, float b, uint32_t& hi, uint32_t& lo) {
    __nv_bfloat16 ha = __float2bfloat16_rn(a);
    __nv_bfloat16 hb = __float2bfloat16_rn(b);
    hi = ((uint32_t)*(unsigned short*)&hb << 16) | *(unsigned short*)&ha;
    lo = packbf(a - __bfloat162float(ha), b - __bfloat162float(hb));
}

// ---------------- fused fp32 -> bf16 hi/lo conversion (8 elems/thread) -------
__global__ void conv_kernel(const float* __restrict__ X,
                            const float* __restrict__ Wq, const float* __restrict__ Wk,
                            const float* __restrict__ Wv, const float* __restrict__ Wo)
{
    const int XN = MROWS * HID;
    const int WN = HID * HID;
    int i8 = (blockIdx.x * 256 + threadIdx.x) * 8;
    const float* src;
    __nv_bfloat16 *dh, *dl;
    int off;
    if (i8 < XN) { src = X; dh = g_Xhi; dl = g_Xlo; off = i8; }
    else {
        int j = i8 - XN;
        int w = j / WN; off = j - w * WN;
        src = (w == 0) ? Wq : (w == 1) ? Wk : (w == 2) ? Wv : Wo;
        dh = g_Whi[w]; dl = g_Wlo[w];
    }
    float4 v0 = *(const float4*)(src + off);
    float4 v1 = *(const float4*)(src + off + 4);
    uint32_t h01, l01, h23, l23, h45, l45, h67, l67;
    split2pack(v0.x, v0.y, h01, l01);
    split2pack(v0.z, v0.w, h23, l23);
    split2pack(v1.x, v1.y, h45, l45);
    split2pack(v1.z, v1.w, h67, l67);
    *(uint4*)(dh + off) = make_uint4(h01, h23, h45, h67);
    *(uint4*)(dl + off) = make_uint4(l01, l23, l45, l67);
}

// ---------------- projection / out-proj GEMM ---------------------------------
// 128x128 tile, K-chunk 32, hi|lo packed rows, 3-stage ring, 1 barrier/chunk,
// lookahead-2, 2 CTAs/SM. RoPE fused into the Q/K epilogue.
__global__ __launch_bounds__(256, 2) void gemm_kernel(int mode, float* __restrict__ out)
{
    extern __shared__ char smem[];
    uint32_t sb = smem_u32(smem);

    int tid = threadIdx.x;
    int wid = tid >> 5, lane = tid & 31;
    int wm = wid & 3, wn = wid >> 2;
    int t = blockIdx.x;

    const __nv_bfloat16 *Ahi, *Alo, *Bhi, *Blo;
    int mtile, ntile, w = 0;
    const int nChunks = 64;

    if (mode == 0) {
        w = t >> 9; int r = t & 511; mtile = r >> 4; ntile = r & 15;
        Ahi = g_Xhi + (size_t)mtile * 128 * HID;
        Alo = g_Xlo + (size_t)mtile * 128 * HID;
        Bhi = g_Whi[w] + (size_t)ntile * 128 * HID;
        Blo = g_Wlo[w] + (size_t)ntile * 128 * HID;
    } else {
        mtile = t >> 4; ntile = t & 15;
        Ahi = g_Chi + (size_t)mtile * 128 * HID;
        Alo = g_Clo + (size_t)mtile * 128 * HID;
        Bhi = g_Whi[3] + (size_t)ntile * 128 * HID;
        Blo = g_Wlo[3] + (size_t)ntile * 128 * HID;
    }

    int lrow[8], lseg[8], lmat[8], lhl[8];
    uint32_t ldst[8];
#pragma unroll
    for (int it = 0; it < 8; it++) {
        int u = tid + it * 256;
        int mat = u >> 10, hl = (u >> 9) & 1, row = (u >> 2) & 127, seg = u & 3;
        lmat[it] = mat; lhl[it] = hl; lrow[it] = row; lseg[it] = seg;
        ldst[it] = mat * 16384 + SWZ(row * 128 + hl * 64 + seg * 16);
    }

    float acc[2][8][4];
#pragma unroll
    for (int mi = 0; mi < 2; mi++)
#pragma unroll
        for (int ni = 0; ni < 8; ni++)
#pragma unroll
            for (int e = 0; e < 4; e++) acc[mi][ni][e] = 0.0f;

    auto issue_load = [&](int c) {
        int koff = c * 32;
        uint32_t base = sb + (c % G_NST) * G_STAGE;
#pragma unroll
        for (int it = 0; it < 8; it++) {
            const __nv_bfloat16* src0 =
                (lmat[it] == 0) ? (lhl[it] ? Alo : Ahi)
                                : (lhl[it] ? Blo : Bhi);
            const __nv_bfloat16* src = src0 + (size_t)lrow[it] * HID + koff + lseg[it] * 8;
            CP16(base + ldst[it], src);
        }
        asm volatile("cp.async.commit_group;" ::: "memory");
    };

    issue_load(0); issue_load(1);

    int a_r = lane & 15, a_h = (lane >> 4) << 4;
    int b_r = lane & 7;
    int b_row = ((lane >> 4) << 3) + b_r;
    int b_h = ((lane >> 3) & 1) << 4;

    for (int c = 0; c < nChunks; c++) {
        if (c + 1 < nChunks) {
            asm volatile("cp.async.wait_group 1;" ::: "memory");
        } else {
            asm volatile("cp.async.wait_group 0;" ::: "memory");
        }
        __syncthreads();

        if (c + 2 < nChunks) issue_load(c + 2);

        uint32_t st = sb + (c % G_NST) * G_STAGE;
        uint32_t aB = st, bB = st + 16384;

#pragma unroll
        for (int kk = 0; kk < 2; kk++) {
            uint32_t ahi[2][4], alo[2][4];
#pragma unroll
            for (int mi = 0; mi < 2; mi++) {
                int row = wm * 32 + mi * 16 + a_r;
                ldsm_x4(ahi[mi], aB + SWZ(row * 128 + kk * 32 + a_h));
                ldsm_x4(alo[mi], aB + SWZ(row * 128 + 64 + kk * 32 + a_h));
            }
#pragma unroll
            for (int np = 0; np < 4; np++) {
                int row = wn * 64 + np * 16 + b_row;
                uint32_t bh[4], bl[4];
                ldsm_x4(bh, bB + SWZ(row * 128 + kk * 32 + b_h));
                ldsm_x4(bl, bB + SWZ(row * 128 + 64 + kk * 32 + b_h));
#pragma unroll
                for (int mi = 0; mi < 2; mi++) {
                    mma16816(acc[mi][2 * np],     ahi[mi], bh[0], bh[1]);
                    mma16816(acc[mi][2 * np + 1], ahi[mi], bh[2], bh[3]);
                    mma16816(acc[mi][2 * np],     ahi[mi], bl[0], bl[1]);
                    mma16816(acc[mi][2 * np + 1], ahi[mi], bl[2], bl[3]);
                    mma16816(acc[mi][2 * np],     alo[mi], bh[0], bh[1]);
                    mma16816(acc[mi][2 * np + 1], alo[mi], bh[2], bh[3]);
                }
            }
        }
    }

    int g = lane >> 2, tq = lane & 3;

    if (mode == 0 && w < 2) {
        // ---- fused RoPE epilogue: stage fp32 tile in smem, rotate, split ----
        float* sf = (float*)smem;
        __syncthreads();
        if (tid < 64)
            sf[16640 + tid] = (float)(1.0 / pow(10000.0, (double)(2 * tid) / 128.0));
#pragma unroll
        for (int mi = 0; mi < 2; mi++)
#pragma unroll
            for (int ni = 0; ni < 8; ni++) {
                int col0 = wn * 64 + ni * 8 + 2 * tq;
#pragma unroll
                for (int half = 0; half < 2; half++) {
                    int row = wm * 32 + mi * 16 + g + half * 8;
                    *(float2*)&sf[row * 130 + col0] =
                        make_float2(acc[mi][ni][2 * half], acc[mi][ni][2 * half + 1]);
                }
            }
        __syncthreads();

        __nv_bfloat16* dh = (w == 0) ? g_Qhi : g_Khi;
        __nv_bfloat16* dl = (w == 0) ? g_Qlo : g_Klo;
        for (int u = tid; u < 128 * 32; u += 256) {
            int r = u >> 5;
            int ip = (u & 31) * 2;
            float x1a = sf[r * 130 + ip],      x1b = sf[r * 130 + ip + 1];
            float x2a = sf[r * 130 + 64 + ip], x2b = sf[r * 130 + 65 + ip];
            int m = mtile * 128 + r;
            int b = m >> 11, sx = m & 2047;
            float fa = (float)sx;
            float anga = fa * sf[16640 + ip];
            float angb = fa * sf[16640 + ip + 1];
            float ca = cosf(anga), sa_ = sinf(anga);
            float cb = cosf(angb), sb_ = sinf(angb);
            float y1a = x1a * ca - x2a * sa_;
            float y2a = x2a * ca + x1a * sa_;
            float y1b = x1b * cb - x2b * sb_;
            float y2b = x2b * cb + x1b * sb_;
            size_t o = ((size_t)(b * NH + ntile) * S_LEN + sx) * HD;
            uint32_t hi, lo;
            split2pack(y1a, y1b, hi, lo);
            *(uint32_t*)(dh + o + ip) = hi;
            *(uint32_t*)(dl + o + ip) = lo;
            split2pack(y2a, y2b, hi, lo);
            *(uint32_t*)(dh + o + 64 + ip) = hi;
            *(uint32_t*)(dl + o + 64 + ip) = lo;
        }
        return;
    }

    // ---- direct epilogue: V (mode 0, w==2) and out-proj (mode 3) ----
#pragma unroll
    for (int mi = 0; mi < 2; mi++) {
#pragma unroll
        for (int ni = 0; ni < 8; ni++) {
            int col0 = wn * 64 + ni * 8 + 2 * tq;
#pragma unroll
            for (int half = 0; half < 2; half++) {
                int row = wm * 32 + mi * 16 + g + half * 8;
                float v0 = acc[mi][ni][2 * half];
                float v1 = acc[mi][ni][2 * half + 1];
                if (mode == 0) {
                    int m = mtile * 128 + row;
                    int b = m >> 11, sx = m & 2047;
                    size_t o = ((size_t)(b * NH + ntile) * S_LEN + sx) * HD + col0;
                    uint32_t hi, lo;
                    split2pack(v0, v1, hi, lo);
                    *(uint32_t*)(g_Vhi + o) = hi;
                    *(uint32_t*)(g_Vlo + o) = lo;
                } else {
                    int m = mtile * 128 + row;
                    *(float2*)(out + (size_t)m * HID + ntile * 128 + col0)
                        = make_float2(v0, v1);
                }
            }
        }
    }
}

// ---------------- fused flash attention: 64-row tiles, 2 CTAs/SM ------------
__global__ __launch_bounds__(128, 2) void flash_kernel()
{
    extern __shared__ char smem[];
    uint32_t sb = smem_u32(smem);
    const uint32_t Qh = sb,          Ql = sb + 16384;
    const uint32_t Kh = sb + 32768,  Kl = sb + 49152;
    const uint32_t Vh = sb + 65536,  Vl = sb + 81920;

    int qt = 31 - blockIdx.x;
    int z = blockIdx.y;
    int tid = threadIdx.x, wid = tid >> 5, lane = tid & 31;
    int g = lane >> 2, tq = lane & 3;

    const __nv_bfloat16* Qhg = g_Qhi + ((size_t)z * S_LEN + qt * 64) * HD;
    const __nv_bfloat16* Qlg = g_Qlo + ((size_t)z * S_LEN + qt * 64) * HD;
    const __nv_bfloat16* Khg = g_Khi + (size_t)z * S_LEN * HD;
    const __nv_bfloat16* Klg = g_Klo + (size_t)z * S_LEN * HD;
    const __nv_bfloat16* Vhg = g_Vhi + (size_t)z * S_LEN * HD;
    const __nv_bfloat16* Vlg = g_Vlo + (size_t)z * S_LEN * HD;

    auto load_mat = [&](uint32_t dstbase, const __nv_bfloat16* src) {
#pragma unroll
        for (int it = 0; it < 8; it++) {
            int u = tid + it * 128;
            int row = u >> 4, c = u & 15;
            uint32_t dst = dstbase + ((c >> 3) << 13) + SWZ(row * 128 + (c & 7) * 16);
            CP16(dst, src + (size_t)row * HD + c * 8);
        }
    };

    load_mat(Qh, Qhg); load_mat(Ql, Qlg);
    asm volatile("cp.async.commit_group;" ::: "memory");
    load_mat(Kh, Khg); load_mat(Kl, Klg);
    asm volatile("cp.async.commit_group;" ::: "memory");
    load_mat(Vh, Vhg); load_mat(Vl, Vlg);
    asm volatile("cp.async.commit_group;" ::: "memory");

    float oc[16][4];
#pragma unroll
    for (int j = 0; j < 16; j++)
#pragma unroll
        for (int e = 0; e < 4; e++) oc[j][e] = 0.0f;
    float m0 = -3.4e38f, m1 = -3.4e38f, l0 = 0.0f, l1 = 0.0f;

    const float scale = 0.08838834764831845f;
    int a_r = lane & 15, a_h = (lane >> 4) << 4;
    int bsel = lane >> 3, br = lane & 7;

    for (int kt = 0; kt <= qt; kt++) {
        asm volatile("cp.async.wait_group 1;" ::: "memory");
        __syncthreads();

        float s[8][4];
#pragma unroll
        for (int j = 0; j < 8; j++)
#pragma unroll
            for (int e = 0; e < 4; e++) s[j][e] = 0.0f;

#pragma unroll
        for (int kk = 0; kk < 8; kk++) {
            int arow = wid * 16 + a_r;
            uint32_t aoff = ((kk >> 2) << 13) + SWZ(arow * 128 + (kk & 3) * 32 + a_h);
            uint32_t ah[4], al[4];
            ldsm_x4(ah, Qh + aoff);
            ldsm_x4(al, Ql + aoff);
#pragma unroll
            for (int jp = 0; jp < 4; jp++) {
                int srow = jp * 16 + ((bsel >> 1) << 3) + br;
                uint32_t boff = ((kk >> 2) << 13)
                              + SWZ(srow * 128 + (kk & 3) * 32 + ((bsel & 1) << 4));
                uint32_t bh[4], bl[4];
                ldsm_x4(bh, Kh + boff);
                ldsm_x4(bl, Kl + boff);
                mma16816(s[2 * jp],     ah, bh[0], bh[1]);
                mma16816(s[2 * jp + 1], ah, bh[2], bh[3]);
                mma16816(s[2 * jp],     ah, bl[0], bl[1]);
                mma16816(s[2 * jp + 1], ah, bl[2], bl[3]);
                mma16816(s[2 * jp],     al, bh[0], bh[1]);
                mma16816(s[2 * jp + 1], al, bh[2], bh[3]);
            }
        }

        bool diag = (kt == qt);
        int row0 = qt * 64 + wid * 16 + g;
        float tm0 = -3.4e38f, tm1 = -3.4e38f;
#pragma unroll
        for (int j = 0; j < 8; j++) {
#pragma unroll
            for (int e = 0; e < 4; e++) {
                float v = s[j][e] * scale;
                if (diag) {
                    int col = kt * 64 + j * 8 + 2 * tq + (e & 1);
                    int row = row0 + ((e >> 1) << 3);
                    if (col > row) v = -3.0e38f;
                }
                s[j][e] = v;
                if (e < 2) tm0 = fmaxf(tm0, v); else tm1 = fmaxf(tm1, v);
            }
        }
        tm0 = fmaxf(tm0, __shfl_xor_sync(0xffffffffu, tm0, 1));
        tm0 = fmaxf(tm0, __shfl_xor_sync(0xffffffffu, tm0, 2));
        tm1 = fmaxf(tm1, __shfl_xor_sync(0xffffffffu, tm1, 1));
        tm1 = fmaxf(tm1, __shfl_xor_sync(0xffffffffu, tm1, 2));
        float nm0 = fmaxf(m0, tm0), nm1 = fmaxf(m1, tm1);
        float f0 = __expf(m0 - nm0), f1 = __expf(m1 - nm1);

        float ts0 = 0.0f, ts1 = 0.0f;
        uint32_t phi[4][4], plo[4][4];
#pragma unroll
        for (int i = 0; i < 4; i++) {
            float p[2][4];
#pragma unroll
            for (int h = 0; h < 2; h++) {
                int j = 2 * i + h;
                p[h][0] = __expf(s[j][0] - nm0);
                p[h][1] = __expf(s[j][1] - nm0);
                p[h][2] = __expf(s[j][2] - nm1);
                p[h][3] = __expf(s[j][3] - nm1);
                ts0 += p[h][0] + p[h][1];
                ts1 += p[h][2] + p[h][3];
            }
            phi[i][0] = packbf(p[0][0], p[0][1]);
            phi[i][1] = packbf(p[0][2], p[0][3]);
            phi[i][2] = packbf(p[1][0], p[1][1]);
            phi[i][3] = packbf(p[1][2], p[1][3]);
#pragma unroll
            for (int r = 0; r < 4; r++) {
                __nv_bfloat162 hb = *(__nv_bfloat162*)&phi[i][r];
                float e0 = ((r & 2) ? p[1] : p[0])[(r & 1) ? 2 : 0] - __bfloat162float(hb.x);
                float e1 = ((r & 2) ? p[1] : p[0])[(r & 1) ? 3 : 1] - __bfloat162float(hb.y);
                plo[i][r] = packbf(e0, e1);
            }
        }
        ts0 += __shfl_xor_sync(0xffffffffu, ts0, 1);
        ts0 += __shfl_xor_sync(0xffffffffu, ts0, 2);
        ts1 += __shfl_xor_sync(0xffffffffu, ts1, 1);
        ts1 += __shfl_xor_sync(0xffffffffu, ts1, 2);
        l0 = l0 * f0 + ts0;
        l1 = l1 * f1 + ts1;
        m0 = nm0; m1 = nm1;
#pragma unroll
        for (int j = 0; j < 16; j++) {
            oc[j][0] *= f0; oc[j][1] *= f0; oc[j][2] *= f1; oc[j][3] *= f1;
        }

        asm volatile("cp.async.wait_group 0;" ::: "memory");
        __syncthreads();
        if (kt < qt) {
            load_mat(Kh, Khg + (size_t)(kt + 1) * 64 * HD);
            load_mat(Kl, Klg + (size_t)(kt + 1) * 64 * HD);
            asm volatile("cp.async.commit_group;" ::: "memory");
        }

#pragma unroll
        for (int i = 0; i < 4; i++) {
            int krow = i * 16 + ((bsel & 1) << 3) + br;
#pragma unroll
            for (int dp = 0; dp < 8; dp++) {
                int dt = 2 * dp + (bsel >> 1);
                uint32_t voff = ((dt >> 3) << 13) + SWZ(krow * 128 + (dt & 7) * 16);
                uint32_t vh[4], vl[4];
                ldsm_x4t(vh, Vh + voff);
                ldsm_x4t(vl, Vl + voff);
                mma16816(oc[2 * dp],     phi[i], vh[0], vh[1]);
                mma16816(oc[2 * dp + 1], phi[i], vh[2], vh[3]);
                mma16816(oc[2 * dp],     phi[i], vl[0], vl[1]);
                mma16816(oc[2 * dp + 1], phi[i], vl[2], vl[3]);
                mma16816(oc[2 * dp],     plo[i], vh[0], vh[1]);
                mma16816(oc[2 * dp + 1], plo[i], vh[2], vh[3]);
            }
        }
        __syncthreads();
        if (kt < qt) {
            load_mat(Vh, Vhg + (size_t)(kt + 1) * 64 * HD);
            load_mat(Vl, Vlg + (size_t)(kt + 1) * 64 * HD);
            asm volatile("cp.async.commit_group;" ::: "memory");
        }
    }

    float inv0 = 1.0f / l0, inv1 = 1.0f / l1;
    int b = z >> 4, hh = z & 15;
    int q0 = qt * 64 + wid * 16 + g;
#pragma unroll
    for (int dt = 0; dt < 16; dt++) {
        int col0 = dt * 8 + 2 * tq;
        size_t o0 = ((size_t)b * S_LEN + q0) * HID + hh * HD + col0;
        size_t o1 = ((size_t)b * S_LEN + q0 + 8) * HID + hh * HD + col0;
        uint32_t hi, lo;
        split2pack(oc[dt][0] * inv0, oc[dt][1] * inv0, hi, lo);
        *(uint32_t*)(g_Chi + o0) = hi;
        *(uint32_t*)(g_Clo + o0) = lo;
        split2pack(oc[dt][2] * inv1, oc[dt][3] * inv1, hi, lo);
        *(uint32_t*)(g_Chi + o1) = hi;
        *(uint32_t*)(g_Clo + o1) = lo;
    }
}

// ---------------------------------------------------------------------------
extern "C" void kernel_launch(void* const* d_in, const int* in_sizes, int n_in,
                              void* d_out, int out_size)
{
    (void)in_sizes; (void)n_in; (void)out_size;
    const float* X  = (const float*)d_in[0];
    const float* Wq = (const float*)d_in[3];
    const float* Wk = (const float*)d_in[4];
    const float* Wv = (const float*)d_in[5];
    const float* Wo = (const float*)d_in[6];
    float* out = (float*)d_out;

    cudaFuncSetAttribute(gemm_kernel,
                         cudaFuncAttributeMaxDynamicSharedMemorySize, SMEM_GEMM);
    cudaFuncSetAttribute(flash_kernel,
                         cudaFuncAttributeMaxDynamicSharedMemorySize, SMEM_FLASH);

    conv_kernel<<<12288, 256>>>(X, Wq, Wk, Wv, Wo);
    gemm_kernel<<<1536, 256, SMEM_GEMM>>>(0, nullptr);     // QKV proj + fused RoPE
    flash_kernel<<<dim3(32, 32), 128, SMEM_FLASH>>>();     // fused attention
    gemm_kernel<<<512, 256, SMEM_GEMM>>>(3, out);          // out proj
}

// round 17
// speedup vs baseline: 1.4512x; 1.4149x over previous
#include <cuda_runtime.h>
#include <cuda_fp16.h>
#include <stdint.h>
#include <math.h>

#define S_LEN 2048
#define HID   2048
#define NH    16
#define HD    128
#define BATCH 2
#define MROWS 4096
#define NBH   32
#define G_STAGE   24576          // A(8KB, 64B rows) + B(16KB, hi|lo 128B rows)
#define G_NST     3
#define SMEM_GEMM (G_NST * G_STAGE)   // 72 KB -> 2 CTAs/SM
#define SMEM_FLASH 81920         // Qf,Kh,Kl,Vh,Vl @ 16KB

// ---------------- scratch globals ------------------------------------------
__device__ __align__(16) __half g_X[MROWS * HID];          // fp16 single
__device__ __align__(16) __half g_Whi[4][HID * HID];       // W*64 split
__device__ __align__(16) __half g_Wlo[4][HID * HID];
__device__ __align__(16) __half g_Q[NBH * S_LEN * HD];     // single
__device__ __align__(16) __half g_Khi[NBH * S_LEN * HD];
__device__ __align__(16) __half g_Klo[NBH * S_LEN * HD];
__device__ __align__(16) __half g_Vhi[NBH * S_LEN * HD];
__device__ __align__(16) __half g_Vlo[NBH * S_LEN * HD];
__device__ __align__(16) __half g_C[MROWS * HID];          // single

// ---------------- helpers ---------------------------------------------------
__device__ __forceinline__ uint32_t smem_u32(const void* p) {
    uint32_t a;
    asm("{ .reg .u64 t; cvta.to.shared.u64 t, %1; cvt.u32.u64 %0, t; }"
        : "=r"(a) : "l"(p));
    return a;
}
#define SWZ(o)   ((o) ^ (((o) >> 3) & 0x70))
#define SWZ64(o) ((o) ^ (((o) >> 3) & 0x30))
#define CP16(dst, src) \
    asm volatile("cp.async.cg.shared.global [%0], [%1], 16;" \
                 :: "r"((uint32_t)(dst)), "l"(src) : "memory")

__device__ __forceinline__ void ldsm_x4(uint32_t r[4], uint32_t addr) {
    asm volatile("ldmatrix.sync.aligned.m8n8.x4.shared.b16 {%0,%1,%2,%3}, [%4];"
        : "=r"(r[0]), "=r"(r[1]), "=r"(r[2]), "=r"(r[3]) : "r"(addr));
}
__device__ __forceinline__ void ldsm_x4t(uint32_t r[4], uint32_t addr) {
    asm volatile("ldmatrix.sync.aligned.m8n8.x4.trans.shared.b16 {%0,%1,%2,%3}, [%4];"
        : "=r"(r[0]), "=r"(r[1]), "=r"(r[2]), "=r"(r[3]) : "r"(addr));
}
__device__ __forceinline__ void mma16816(float d[4], const uint32_t a[4],
                                         const uint32_t b0, const uint32_t b1) {
    asm volatile("mma.sync.aligned.m16n8k16.row.col.f32.f16.f16.f32 "
        "{%0,%1,%2,%3}, {%4,%5,%6,%7}, {%8,%9}, {%0,%1,%2,%3};"
        : "+f"(d[0]), "+f"(d[1]), "+f"(d[2]), "+f"(d[3])
        : "r"(a[0]), "r"(a[1]), "r"(a[2]), "r"(a[3]), "r"(b0), "r"(b1));
}
__device__ __forceinline__ uint32_t packh(float a, float b) {
    __half2 t = __floats2half2_rn(a, b);           // a -> .x (low)
    return *(uint32_t*)&t;
}
__device__ __forceinline__ void split2packh(float a, float b, uint32_t& hi, uint32_t& lo) {
    __half ha = __float2half_rn(a);
    __half hb = __float2half_rn(b);
    hi = ((uint32_t)*(unsigned short*)&hb << 16) | *(unsigned short*)&ha;
    lo = packh(a - __half2float(ha), b - __half2float(hb));
}

// ---------------- fp32 -> fp16 conversion (X single, W*64 split) -------------
__global__ void conv_kernel(const float* __restrict__ X,
                            const float* __restrict__ Wq, const float* __restrict__ Wk,
                            const float* __restrict__ Wv, const float* __restrict__ Wo)
{
    const int XN = MROWS * HID;
    const int WN = HID * HID;
    int i8 = (blockIdx.x * 256 + threadIdx.x) * 8;
    if (i8 < XN) {
        float4 v0 = *(const float4*)(X + i8);
        float4 v1 = *(const float4*)(X + i8 + 4);
        uint4 o;
        o.x = packh(v0.x, v0.y); o.y = packh(v0.z, v0.w);
        o.z = packh(v1.x, v1.y); o.w = packh(v1.z, v1.w);
        *(uint4*)(g_X + i8) = o;
    } else {
        int j = i8 - XN;
        int w = j / WN; int off = j - w * WN;
        const float* src = (w == 0) ? Wq : (w == 1) ? Wk : (w == 2) ? Wv : Wo;
        float4 v0 = *(const float4*)(src + off);
        float4 v1 = *(const float4*)(src + off + 4);
        uint32_t h01, l01, h23, l23, h45, l45, h67, l67;
        split2packh(v0.x * 64.0f, v0.y * 64.0f, h01, l01);
        split2packh(v0.z * 64.0f, v0.w * 64.0f, h23, l23);
        split2packh(v1.x * 64.0f, v1.y * 64.0f, h45, l45);
        split2packh(v1.z * 64.0f, v1.w * 64.0f, h67, l67);
        *(uint4*)(g_Whi[w] + off) = make_uint4(h01, h23, h45, h67);
        *(uint4*)(g_Wlo[w] + off) = make_uint4(l01, l23, l45, l67);
    }
}

// ---------------- projection / out-proj GEMM ---------------------------------
// 128x128 tile, K-chunk 32. A: fp16 single (64B rows, SW64). B: W*64 hi|lo
// (128B rows, SW128). 2 MMA terms. 3-stage ring, 1 barrier/chunk, 2 CTAs/SM.
// Epilogue scales by 1/64; RoPE fused for Q/K.
__global__ __launch_bounds__(256, 2) void gemm_kernel(int mode, float* __restrict__ out)
{
    extern __shared__ char smem[];
    uint32_t sb = smem_u32(smem);

    int tid = threadIdx.x;
    int wid = tid >> 5, lane = tid & 31;
    int wm = wid & 3, wn = wid >> 2;
    int t = blockIdx.x;

    const __half *Af, *Bhi, *Blo;
    int mtile, ntile, w = 0;
    const int nChunks = 64;

    if (mode == 0) {
        w = t >> 9; int r = t & 511; mtile = r >> 4; ntile = r & 15;
        Af  = g_X + (size_t)mtile * 128 * HID;
        Bhi = g_Whi[w] + (size_t)ntile * 128 * HID;
        Blo = g_Wlo[w] + (size_t)ntile * 128 * HID;
    } else {
        mtile = t >> 4; ntile = t & 15;
        Af  = g_C + (size_t)mtile * 128 * HID;
        Bhi = g_Whi[3] + (size_t)ntile * 128 * HID;
        Blo = g_Wlo[3] + (size_t)ntile * 128 * HID;
    }

    // per-stage: 1536 x 16B transfers; 6 per thread.
    int lrow[6], lseg[6], lkind[6];       // kind: 0=A, 1=Bhi, 2=Blo
    uint32_t ldst[6];
#pragma unroll
    for (int it = 0; it < 6; it++) {
        int u = tid + it * 256;
        if (u < 512) {
            int row = u >> 2, seg = u & 3;
            lkind[it] = 0; lrow[it] = row; lseg[it] = seg;
            ldst[it] = SWZ64(row * 64 + seg * 16);
        } else {
            int v = u - 512;
            int row = v >> 3, idx = v & 7, hl = idx >> 2, seg = idx & 3;
            lkind[it] = 1 + hl; lrow[it] = row; lseg[it] = seg;
            ldst[it] = 8192 + SWZ(row * 128 + hl * 64 + seg * 16);
        }
    }

    float acc[2][8][4];
#pragma unroll
    for (int mi = 0; mi < 2; mi++)
#pragma unroll
        for (int ni = 0; ni < 8; ni++)
#pragma unroll
            for (int e = 0; e < 4; e++) acc[mi][ni][e] = 0.0f;

    auto issue_load = [&](int c) {
        int koff = c * 32;
        uint32_t base = sb + (c % G_NST) * G_STAGE;
#pragma unroll
        for (int it = 0; it < 6; it++) {
            const __half* src0 = (lkind[it] == 0) ? Af : (lkind[it] == 1) ? Bhi : Blo;
            const __half* src = src0 + (size_t)lrow[it] * HID + koff + lseg[it] * 8;
            CP16(base + ldst[it], src);
        }
        asm volatile("cp.async.commit_group;" ::: "memory");
    };

    issue_load(0); issue_load(1);

    int a_r = lane & 15, a_h = (lane >> 4) << 4;
    int b_r = lane & 7;
    int b_row = ((lane >> 4) << 3) + b_r;
    int b_h = ((lane >> 3) & 1) << 4;

    for (int c = 0; c < nChunks; c++) {
        if (c + 1 < nChunks) {
            asm volatile("cp.async.wait_group 1;" ::: "memory");
        } else {
            asm volatile("cp.async.wait_group 0;" ::: "memory");
        }
        __syncthreads();

        if (c + 2 < nChunks) issue_load(c + 2);

        uint32_t st = sb + (c % G_NST) * G_STAGE;
        uint32_t aB = st, bB = st + 8192;

#pragma unroll
        for (int kk = 0; kk < 2; kk++) {
            uint32_t af[2][4];
#pragma unroll
            for (int mi = 0; mi < 2; mi++) {
                int row = wm * 32 + mi * 16 + a_r;
                ldsm_x4(af[mi], aB + SWZ64(row * 64 + kk * 32 + a_h));
            }
#pragma unroll
            for (int np = 0; np < 4; np++) {
                int row = wn * 64 + np * 16 + b_row;
                uint32_t bh[4], bl[4];
                ldsm_x4(bh, bB + SWZ(row * 128 + kk * 32 + b_h));
                ldsm_x4(bl, bB + SWZ(row * 128 + 64 + kk * 32 + b_h));
#pragma unroll
                for (int mi = 0; mi < 2; mi++) {
                    mma16816(acc[mi][2 * np],     af[mi], bh[0], bh[1]);
                    mma16816(acc[mi][2 * np + 1], af[mi], bh[2], bh[3]);
                    mma16816(acc[mi][2 * np],     af[mi], bl[0], bl[1]);
                    mma16816(acc[mi][2 * np + 1], af[mi], bl[2], bl[3]);
                }
            }
        }
    }

    int g = lane >> 2, tq = lane & 3;
    const float invS = 0.015625f;          // 1/64 (undo weight scaling)

    if (mode == 0 && w < 2) {
        // ---- fused RoPE epilogue: stage fp32 tile in smem, rotate, store ----
        float* sf = (float*)smem;
        __syncthreads();
        if (tid < 64)
            sf[16640 + tid] = (float)(1.0 / pow(10000.0, (double)(2 * tid) / 128.0));
#pragma unroll
        for (int mi = 0; mi < 2; mi++)
#pragma unroll
            for (int ni = 0; ni < 8; ni++) {
                int col0 = wn * 64 + ni * 8 + 2 * tq;
#pragma unroll
                for (int half = 0; half < 2; half++) {
                    int row = wm * 32 + mi * 16 + g + half * 8;
                    *(float2*)&sf[row * 130 + col0] =
                        make_float2(acc[mi][ni][2 * half] * invS,
                                    acc[mi][ni][2 * half + 1] * invS);
                }
            }
        __syncthreads();

        for (int u = tid; u < 128 * 32; u += 256) {
            int r = u >> 5;
            int ip = (u & 31) * 2;
            float x1a = sf[r * 130 + ip],      x1b = sf[r * 130 + ip + 1];
            float x2a = sf[r * 130 + 64 + ip], x2b = sf[r * 130 + 65 + ip];
            int m = mtile * 128 + r;
            int b = m >> 11, sx = m & 2047;
            float fa = (float)sx;
            float anga = fa * sf[16640 + ip];
            float angb = fa * sf[16640 + ip + 1];
            float ca = cosf(anga), sa_ = sinf(anga);
            float cb = cosf(angb), sb_ = sinf(angb);
            float y1a = x1a * ca - x2a * sa_;
            float y2a = x2a * ca + x1a * sa_;
            float y1b = x1b * cb - x2b * sb_;
            float y2b = x2b * cb + x1b * sb_;
            size_t o = ((size_t)(b * NH + ntile) * S_LEN + sx) * HD;
            if (w == 0) {
                *(uint32_t*)(g_Q + o + ip)      = packh(y1a, y1b);
                *(uint32_t*)(g_Q + o + 64 + ip) = packh(y2a, y2b);
            } else {
                uint32_t hi, lo;
                split2packh(y1a, y1b, hi, lo);
                *(uint32_t*)(g_Khi + o + ip) = hi;
                *(uint32_t*)(g_Klo + o + ip) = lo;
                split2packh(y2a, y2b, hi, lo);
                *(uint32_t*)(g_Khi + o + 64 + ip) = hi;
                *(uint32_t*)(g_Klo + o + 64 + ip) = lo;
            }
        }
        return;
    }

    // ---- direct epilogue: V (mode 0, w==2) and out-proj (mode 3) ----
#pragma unroll
    for (int mi = 0; mi < 2; mi++) {
#pragma unroll
        for (int ni = 0; ni < 8; ni++) {
            int col0 = wn * 64 + ni * 8 + 2 * tq;
#pragma unroll
            for (int half = 0; half < 2; half++) {
                int row = wm * 32 + mi * 16 + g + half * 8;
                float v0 = acc[mi][ni][2 * half] * invS;
                float v1 = acc[mi][ni][2 * half + 1] * invS;
                if (mode == 0) {
                    int m = mtile * 128 + row;
                    int b = m >> 11, sx = m & 2047;
                    size_t o = ((size_t)(b * NH + ntile) * S_LEN + sx) * HD + col0;
                    uint32_t hi, lo;
                    split2packh(v0, v1, hi, lo);
                    *(uint32_t*)(g_Vhi + o) = hi;
                    *(uint32_t*)(g_Vlo + o) = lo;
                } else {
                    int m = mtile * 128 + row;
                    *(float2*)(out + (size_t)m * HID + ntile * 128 + col0)
                        = make_float2(v0, v1);
                }
            }
        }
    }
}

// ---------------- fused flash attention: fp16 2-term, 2 CTAs/SM --------------
// Q single; K hi/lo; V hi/lo; P single fp16 (no plo).
__global__ __launch_bounds__(128, 2) void flash_kernel()
{
    extern __shared__ char smem[];
    uint32_t sb = smem_u32(smem);
    const uint32_t Qf = sb;
    const uint32_t Kh = sb + 16384, Kl = sb + 32768;
    const uint32_t Vh = sb + 49152, Vl = sb + 65536;

    int qt = 31 - blockIdx.x;
    int z = blockIdx.y;
    int tid = threadIdx.x, wid = tid >> 5, lane = tid & 31;
    int g = lane >> 2, tq = lane & 3;

    const __half* Qg  = g_Q   + ((size_t)z * S_LEN + qt * 64) * HD;
    const __half* Khg = g_Khi + (size_t)z * S_LEN * HD;
    const __half* Klg = g_Klo + (size_t)z * S_LEN * HD;
    const __half* Vhg = g_Vhi + (size_t)z * S_LEN * HD;
    const __half* Vlg = g_Vlo + (size_t)z * S_LEN * HD;

    auto load_mat = [&](uint32_t dstbase, const __half* src) {
#pragma unroll
        for (int it = 0; it < 8; it++) {
            int u = tid + it * 128;
            int row = u >> 4, c = u & 15;
            uint32_t dst = dstbase + ((c >> 3) << 13) + SWZ(row * 128 + (c & 7) * 16);
            CP16(dst, src + (size_t)row * HD + c * 8);
        }
    };

    load_mat(Qf, Qg);
    asm volatile("cp.async.commit_group;" ::: "memory");
    load_mat(Kh, Khg); load_mat(Kl, Klg);
    asm volatile("cp.async.commit_group;" ::: "memory");
    load_mat(Vh, Vhg); load_mat(Vl, Vlg);
    asm volatile("cp.async.commit_group;" ::: "memory");

    float oc[16][4];
#pragma unroll
    for (int j = 0; j < 16; j++)
#pragma unroll
        for (int e = 0; e < 4; e++) oc[j][e] = 0.0f;
    float m0 = -3.4e38f, m1 = -3.4e38f, l0 = 0.0f, l1 = 0.0f;

    const float scale = 0.08838834764831845f;
    int a_r = lane & 15, a_h = (lane >> 4) << 4;
    int bsel = lane >> 3, br = lane & 7;

    for (int kt = 0; kt <= qt; kt++) {
        asm volatile("cp.async.wait_group 1;" ::: "memory");
        __syncthreads();

        float s[8][4];
#pragma unroll
        for (int j = 0; j < 8; j++)
#pragma unroll
            for (int e = 0; e < 4; e++) s[j][e] = 0.0f;

#pragma unroll
        for (int kk = 0; kk < 8; kk++) {
            int arow = wid * 16 + a_r;
            uint32_t aoff = ((kk >> 2) << 13) + SWZ(arow * 128 + (kk & 3) * 32 + a_h);
            uint32_t aq[4];
            ldsm_x4(aq, Qf + aoff);
#pragma unroll
            for (int jp = 0; jp < 4; jp++) {
                int srow = jp * 16 + ((bsel >> 1) << 3) + br;
                uint32_t boff = ((kk >> 2) << 13)
                              + SWZ(srow * 128 + (kk & 3) * 32 + ((bsel & 1) << 4));
                uint32_t bh[4], bl[4];
                ldsm_x4(bh, Kh + boff);
                ldsm_x4(bl, Kl + boff);
                mma16816(s[2 * jp],     aq, bh[0], bh[1]);
                mma16816(s[2 * jp + 1], aq, bh[2], bh[3]);
                mma16816(s[2 * jp],     aq, bl[0], bl[1]);
                mma16816(s[2 * jp + 1], aq, bl[2], bl[3]);
            }
        }

        bool diag = (kt == qt);
        int row0 = qt * 64 + wid * 16 + g;
        float tm0 = -3.4e38f, tm1 = -3.4e38f;
#pragma unroll
        for (int j = 0; j < 8; j++) {
#pragma unroll
            for (int e = 0; e < 4; e++) {
                float v = s[j][e] * scale;
                if (diag) {
                    int col = kt * 64 + j * 8 + 2 * tq + (e & 1);
                    int row = row0 + ((e >> 1) << 3);
                    if (col > row) v = -3.0e38f;
                }
                s[j][e] = v;
                if (e < 2) tm0 = fmaxf(tm0, v); else tm1 = fmaxf(tm1, v);
            }
        }
        tm0 = fmaxf(tm0, __shfl_xor_sync(0xffffffffu, tm0, 1));
        tm0 = fmaxf(tm0, __shfl_xor_sync(0xffffffffu, tm0, 2));
        tm1 = fmaxf(tm1, __shfl_xor_sync(0xffffffffu, tm1, 1));
        tm1 = fmaxf(tm1, __shfl_xor_sync(0xffffffffu, tm1, 2));
        float nm0 = fmaxf(m0, tm0), nm1 = fmaxf(m1, tm1);
        float f0 = __expf(m0 - nm0), f1 = __expf(m1 - nm1);

        float ts0 = 0.0f, ts1 = 0.0f;
        uint32_t phi[4][4];
#pragma unroll
        for (int i = 0; i < 4; i++) {
            float p[2][4];
#pragma unroll
            for (int h = 0; h < 2; h++) {
                int j = 2 * i + h;
                p[h][0] = __expf(s[j][0] - nm0);
                p[h][1] = __expf(s[j][1] - nm0);
                p[h][2] = __expf(s[j][2] - nm1);
                p[h][3] = __expf(s[j][3] - nm1);
                ts0 += p[h][0] + p[h][1];
                ts1 += p[h][2] + p[h][3];
            }
            phi[i][0] = packh(p[0][0], p[0][1]);
            phi[i][1] = packh(p[0][2], p[0][3]);
            phi[i][2] = packh(p[1][0], p[1][1]);
            phi[i][3] = packh(p[1][2], p[1][3]);
        }
        ts0 += __shfl_xor_sync(0xffffffffu, ts0, 1);
        ts0 += __shfl_xor_sync(0xffffffffu, ts0, 2);
        ts1 += __shfl_xor_sync(0xffffffffu, ts1, 1);
        ts1 += __shfl_xor_sync(0xffffffffu, ts1, 2);
        l0 = l0 * f0 + ts0;
        l1 = l1 * f1 + ts1;
        m0 = nm0; m1 = nm1;
#pragma unroll
        for (int j = 0; j < 16; j++) {
            oc[j][0] *= f0; oc[j][1] *= f0; oc[j][2] *= f1; oc[j][3] *= f1;
        }

        asm volatile("cp.async.wait_group 0;" ::: "memory");
        __syncthreads();
        if (kt < qt) {
            load_mat(Kh, Khg + (size_t)(kt + 1) * 64 * HD);
            load_mat(Kl, Klg + (size_t)(kt + 1) * 64 * HD);
            asm volatile("cp.async.commit_group;" ::: "memory");
        }

#pragma unroll
        for (int i = 0; i < 4; i++) {
            int krow = i * 16 + ((bsel & 1) << 3) + br;
#pragma unroll
            for (int dp = 0; dp < 8; dp++) {
                int dt = 2 * dp + (bsel >> 1);
                uint32_t voff = ((dt >> 3) << 13) + SWZ(krow * 128 + (dt & 7) * 16);
                uint32_t vh[4], vl[4];
                ldsm_x4t(vh, Vh + voff);
                ldsm_x4t(vl, Vl + voff);
                mma16816(oc[2 * dp],     phi[i], vh[0], vh[1]);
                mma16816(oc[2 * dp + 1], phi[i], vh[2], vh[3]);
                mma16816(oc[2 * dp],     phi[i], vl[0], vl[1]);
                mma16816(oc[2 * dp + 1], phi[i], vl[2], vl[3]);
            }
        }
        __syncthreads();
        if (kt < qt) {
            load_mat(Vh, Vhg + (size_t)(kt + 1) * 64 * HD);
            load_mat(Vl, Vlg + (size_t)(kt + 1) * 64 * HD);
            asm volatile("cp.async.commit_group;" ::: "memory");
        }
    }

    float inv0 = 1.0f / l0, inv1 = 1.0f / l1;
    int b = z >> 4, hh = z & 15;
    int q0 = qt * 64 + wid * 16 + g;
#pragma unroll
    for (int dt = 0; dt < 16; dt++) {
        int col0 = dt * 8 + 2 * tq;
        size_t o0 = ((size_t)b * S_LEN + q0) * HID + hh * HD + col0;
        size_t o1 = ((size_t)b * S_LEN + q0 + 8) * HID + hh * HD + col0;
        *(uint32_t*)(g_C + o0) = packh(oc[dt][0] * inv0, oc[dt][1] * inv0);
        *(uint32_t*)(g_C + o1) = packh(oc[dt][2] * inv1, oc[dt][3] * inv1);
    }
}

// ---------------------------------------------------------------------------
extern "C" void kernel_launch(void* const* d_in, const int* in_sizes, int n_in,
                              void* d_out, int out_size)
{
    (void)in_sizes; (void)n_in; (void)out_size;
    const float* X  = (const float*)d_in[0];
    const float* Wq = (const float*)d_in[3];
    const float* Wk = (const float*)d_in[4];
    const float* Wv = (const float*)d_in[5];
    const float* Wo = (const float*)d_in[6];
    float* out = (float*)d_out;

    cudaFuncSetAttribute(gemm_kernel,
                         cudaFuncAttributeMaxDynamicSharedMemorySize, SMEM_GEMM);
    cudaFuncSetAttribute(flash_kernel,
                         cudaFuncAttributeMaxDynamicSharedMemorySize, SMEM_FLASH);

    conv_kernel<<<12288, 256>>>(X, Wq, Wk, Wv, Wo);
    gemm_kernel<<<1536, 256, SMEM_GEMM>>>(0, nullptr);     // QKV proj + fused RoPE
    flash_kernel<<<dim3(32, 32), 128, SMEM_FLASH>>>();     // fused attention
    gemm_kernel<<<512, 256, SMEM_GEMM>>>(3, out);          // out proj
}